// round 3
// baseline (speedup 1.0000x reference)
#include <cuda_runtime.h>

// Problem constants
#define BN 4096          // batch
#define DD 512           // feature dim
#define T_TILES 32       // 4096 / 128
#define NTRI   528       // T_TILES*(T_TILES+1)/2
#define TM 128
#define TN 128
#define TK 16
// number of pairs: 4096*4095/2
#define NPAIRS 8386560.0

// Scratch (no allocations allowed)
__device__ float  g_invn[BN];
__device__ int    g_code[BN];
__device__ double g_acc;

// ---------------------------------------------------------------------------
// Kernel 1: per-row inverse norm (warp per row), label/animacy codes, zero acc
// NOTE: labels arrive as int32 (JAX default x64-disabled downcasts int64).
// ---------------------------------------------------------------------------
__global__ void prep_kernel(const float* __restrict__ x,
                            const int* __restrict__ labels,
                            const int* __restrict__ anim) {
    int gtid = blockIdx.x * blockDim.x + threadIdx.x;
    int warp = gtid >> 5;
    int lane = threadIdx.x & 31;

    if (warp < BN) {
        const float4* row = reinterpret_cast<const float4*>(x + (size_t)warp * DD);
        float s = 0.f;
        #pragma unroll
        for (int k = lane; k < DD / 4; k += 32) {
            float4 v = row[k];
            s += v.x * v.x + v.y * v.y + v.z * v.z + v.w * v.w;
        }
        #pragma unroll
        for (int off = 16; off; off >>= 1) s += __shfl_xor_sync(0xffffffffu, s, off);
        if (lane == 0) g_invn[warp] = 1.0f / fmaxf(sqrtf(s), 1e-8f);
    }
    if (gtid < BN) {
        int lab = labels[gtid];
        lab = min(max(lab, 0), 15);              // defensive clamp (no OOB on anim)
        g_code[gtid] = lab | (anim[lab] << 8);   // same label => identical code
    }
    if (gtid == 0) g_acc = 0.0;
}

// ---------------------------------------------------------------------------
// Kernel 2: fused tiled gram + loss epilogue, triangular grid (528 CTAs).
// 128x128 tile per block, TK=16 k-slice, 256 threads, 8x8 per thread.
// ---------------------------------------------------------------------------
__global__ __launch_bounds__(256, 2)
void gemm_loss_kernel(const float* __restrict__ x) {
    // Decode linear block index b -> (ti, tj) with ti <= tj.
    // Enumeration: b = tj*(tj+1)/2 + ti, ti in [0, tj].
    int b = blockIdx.x;
    int tj = (int)((sqrtf(8.0f * (float)b + 1.0f) - 1.0f) * 0.5f);
    // correct rounding
    while (tj * (tj + 1) / 2 > b) tj--;
    while ((tj + 1) * (tj + 2) / 2 <= b) tj++;
    int ti = b - tj * (tj + 1) / 2;

    __shared__ float As[TK][TM];
    __shared__ float Bs[TK][TN];

    const int tid = threadIdx.x;
    const int tx  = tid & 15;    // 0..15 -> 8 cols each
    const int ty  = tid >> 4;    // 0..15 -> 8 rows each
    const int row0 = ti * TM;
    const int col0 = tj * TN;

    float acc[8][8];
    #pragma unroll
    for (int i = 0; i < 8; i++)
        #pragma unroll
        for (int j = 0; j < 8; j++) acc[i][j] = 0.f;

    for (int k0 = 0; k0 < DD; k0 += TK) {
        __syncthreads();
        // Load both 128x16 slices (transposed into [k][m]) with float4 reads.
        #pragma unroll
        for (int p = 0; p < 2; p++) {
            int idx = tid + p * 256;       // 0..511
            int r   = idx >> 2;            // 0..127
            int kv  = idx & 3;             // which float4 along k
            const float4 va = *reinterpret_cast<const float4*>(
                x + (size_t)(row0 + r) * DD + k0 + kv * 4);
            const float4 vb = *reinterpret_cast<const float4*>(
                x + (size_t)(col0 + r) * DD + k0 + kv * 4);
            As[kv * 4 + 0][r] = va.x; As[kv * 4 + 1][r] = va.y;
            As[kv * 4 + 2][r] = va.z; As[kv * 4 + 3][r] = va.w;
            Bs[kv * 4 + 0][r] = vb.x; Bs[kv * 4 + 1][r] = vb.y;
            Bs[kv * 4 + 2][r] = vb.z; Bs[kv * 4 + 3][r] = vb.w;
        }
        __syncthreads();

        #pragma unroll
        for (int k = 0; k < TK; k++) {
            float a[8], bb[8];
            *(float4*)&a[0]  = *(const float4*)&As[k][ty * 8];
            *(float4*)&a[4]  = *(const float4*)&As[k][ty * 8 + 4];
            *(float4*)&bb[0] = *(const float4*)&Bs[k][tx * 8];
            *(float4*)&bb[4] = *(const float4*)&Bs[k][tx * 8 + 4];
            #pragma unroll
            for (int i = 0; i < 8; i++)
                #pragma unroll
                for (int j = 0; j < 8; j++)
                    acc[i][j] = fmaf(a[i], bb[j], acc[i][j]);
        }
    }

    // -------- epilogue: per-pair loss --------
    float invi[8], invj[8];
    int   ci[8],   cj[8];
    #pragma unroll
    for (int i = 0; i < 8; i++) {
        int gi = row0 + ty * 8 + i;
        invi[i] = g_invn[gi];
        ci[i]   = g_code[gi];
    }
    #pragma unroll
    for (int j = 0; j < 8; j++) {
        int gj = col0 + tx * 8 + j;
        invj[j] = g_invn[gj];
        cj[j]   = g_code[gj];
    }

    float loss = 0.f;
    #pragma unroll
    for (int i = 0; i < 8; i++) {
        int gi = row0 + ty * 8 + i;
        #pragma unroll
        for (int j = 0; j < 8; j++) {
            int gj = col0 + tx * 8 + j;
            if (gj > gi) {
                float c = acc[i][j] * invi[i] * invj[j];   // cosine similarity
                float t;
                if (ci[i] == cj[j]) {
                    // positive pair: max((1-c) - 0.05, 0)^2
                    t = fmaxf(0.95f - c, 0.f);
                } else {
                    // negative pair: margin 0.3 if same animacy else 0.5
                    // max(m - (1-c), 0) = max(c - (1-m), 0)
                    float thr = ((ci[i] ^ cj[j]) & 0x100) ? 0.5f : 0.7f;
                    t = fmaxf(c - thr, 0.f);
                }
                loss = fmaf(t, t, loss);
            }
        }
    }

    // block reduction
    __shared__ float red[256];
    red[tid] = loss;
    __syncthreads();
    #pragma unroll
    for (int s = 128; s > 0; s >>= 1) {
        if (tid < s) red[tid] += red[tid + s];
        __syncthreads();
    }
    if (tid == 0) atomicAdd(&g_acc, (double)red[0]);
}

// ---------------------------------------------------------------------------
// Kernel 3: finalize
// ---------------------------------------------------------------------------
__global__ void finalize_kernel(float* out) {
    out[0] = (float)(g_acc / NPAIRS);
}

extern "C" void kernel_launch(void* const* d_in, const int* in_sizes, int n_in,
                              void* d_out, int out_size) {
    const float* x      = (const float*)d_in[0];
    const int*   labels = (const int*)d_in[1];
    const int*   anim   = (const int*)d_in[2];
    float*       out    = (float*)d_out;

    // 4096 rows, warp per row -> 4096 warps -> 512 blocks x 256 threads
    prep_kernel<<<512, 256>>>(x, labels, anim);

    gemm_loss_kernel<<<NTRI, 256>>>(x);

    finalize_kernel<<<1, 1>>>(out);
}

// round 7
// speedup vs baseline: 4.9927x; 4.9927x over previous
#include <cuda_runtime.h>
#include <cuda_fp16.h>
#include <cstdint>

// Problem constants
#define BN 4096          // batch
#define DD 512           // feature dim
#define T_TILES 32       // 4096 / 128
#define NTRI   528       // T_TILES*(T_TILES+1)/2
#define NPAIRS 8386560.0

// CTA tile
#define TM 128
#define TN 128
#define KC 64            // k-chunk (fp16 elems) => 128 bytes/row, SW128 swizzle
#define NCHUNK (DD / KC) // 8

// Scratch (no allocations allowed)
__device__ __half  g_xh[BN * DD];   // normalized rows in fp16 (4 MB)
__device__ int     g_code[BN];
__device__ double  g_acc;

__device__ __forceinline__ uint32_t swz(uint32_t off) {
    // SW128: XOR 16B-chunk bits[4:6] with row bits[7:9]
    return off ^ ((off >> 3) & 0x70);
}

// ---------------------------------------------------------------------------
// Kernel 1: warp per row -> inv-norm, write normalized fp16 row; codes; acc=0
// ---------------------------------------------------------------------------
__global__ void prep_kernel(const float* __restrict__ x,
                            const int* __restrict__ labels,
                            const int* __restrict__ anim) {
    int gtid = blockIdx.x * blockDim.x + threadIdx.x;
    int row  = gtid >> 5;
    int lane = threadIdx.x & 31;

    if (row < BN) {
        const float4* rf4 = reinterpret_cast<const float4*>(x + (size_t)row * DD);
        float s = 0.f;
        #pragma unroll
        for (int k = lane; k < DD / 4; k += 32) {
            float4 v = rf4[k];
            s += v.x * v.x + v.y * v.y + v.z * v.z + v.w * v.w;
        }
        #pragma unroll
        for (int off = 16; off; off >>= 1) s += __shfl_xor_sync(0xffffffffu, s, off);
        float inv = 1.0f / fmaxf(sqrtf(s), 1e-8f);

        uint2* dst = reinterpret_cast<uint2*>(g_xh + (size_t)row * DD);
        #pragma unroll
        for (int k0 = 0; k0 < 4; k0++) {
            int e4 = k0 * 32 + lane;            // float4 index 0..127
            float4 v = rf4[e4];
            __half2 lo = __float22half2_rn(make_float2(v.x * inv, v.y * inv));
            __half2 hi = __float22half2_rn(make_float2(v.z * inv, v.w * inv));
            uint2 packed;
            packed.x = *reinterpret_cast<uint32_t*>(&lo);
            packed.y = *reinterpret_cast<uint32_t*>(&hi);
            dst[e4] = packed;
        }
    }
    if (gtid < BN) {
        int lab = labels[gtid];
        lab = min(max(lab, 0), 15);
        g_code[gtid] = lab | (anim[lab] << 8);
    }
    if (gtid == 0) g_acc = 0.0;
}

// ---------------------------------------------------------------------------
// Kernel 2: fp16 tensor-core gram + fused loss, triangular grid (528 CTAs).
// 128x128 CTA tile, 8 warps (2x4), warp tile 64x32 via mma.m16n8k16.f16.
// KC=64 chunks, FULL row load (2048 x 16B), cp.async double buffer, SW128.
// ---------------------------------------------------------------------------
extern __shared__ unsigned char smem_dyn[];   // 2 bufs x 2 tiles x 16KB = 64KB

__global__ __launch_bounds__(256, 2)
void gemm_loss_kernel() {
    // Decode linear block index b -> (ti, tj), ti <= tj.
    int b = blockIdx.x;
    int tj = (int)((sqrtf(8.0f * (float)b + 1.0f) - 1.0f) * 0.5f);
    while (tj * (tj + 1) / 2 > b) tj--;
    while ((tj + 1) * (tj + 2) / 2 <= b) tj++;
    int ti = b - tj * (tj + 1) / 2;

    const int row0 = ti * TM;
    const int col0 = tj * TN;

    const int tid  = threadIdx.x;
    const int lane = tid & 31;
    const int w    = tid >> 5;
    const int wm   = w >> 2;          // 0..1
    const int wn   = w & 3;           // 0..3

    const uint32_t smem_base = (uint32_t)__cvta_generic_to_shared(smem_dyn);

    float acc[4][4][4];
    #pragma unroll
    for (int i = 0; i < 4; i++)
        #pragma unroll
        for (int j = 0; j < 4; j++)
            #pragma unroll
            for (int c = 0; c < 4; c++) acc[i][j][c] = 0.f;

    // ---- full-tile cp.async issue: 2048 x 16B (8 per thread) ----
    auto issue = [&](int ch, int buf) {
        #pragma unroll
        for (int i = 0; i < 8; i++) {
            int idx  = tid + i * 256;          // 0..2047
            int tile = idx >> 10;              // 0: A(rows), 1: B(cols)
            int t10  = idx & 1023;
            int r    = t10 >> 3;               // 0..127
            int c    = t10 & 7;                // 16B chunk 0..7 (FULL 128B row)
            int grow = (tile ? col0 : row0) + r;
            const char* gp = reinterpret_cast<const char*>(g_xh)
                           + ((size_t)grow * DD + ch * KC + c * 8) * 2;
            uint32_t sa = smem_base + buf * 32768 + tile * 16384
                        + swz((uint32_t)(r * 128 + c * 16));
            asm volatile("cp.async.cg.shared.global [%0], [%1], 16;\n"
                         :: "r"(sa), "l"(gp));
        }
        asm volatile("cp.async.commit_group;\n" ::);
    };

    issue(0, 0);

    // ldmatrix lane address components
    const int arow = lane & 15;        // A: row within 16
    const int akh  = lane >> 4;        // A: k-half (0/1) -> +8 fp16
    const int brow = lane & 7;         // B: row within 8
    const int bkh  = (lane >> 3) & 1;  // B: k-half

    for (int ch = 0; ch < NCHUNK; ch++) {
        if (ch + 1 < NCHUNK) {
            issue(ch + 1, (ch + 1) & 1);
            asm volatile("cp.async.wait_group 1;\n" ::);
        } else {
            asm volatile("cp.async.wait_group 0;\n" ::);
        }
        __syncthreads();

        const uint32_t Ab = smem_base + (ch & 1) * 32768;
        const uint32_t Bb = Ab + 16384;

        #pragma unroll
        for (int ks = 0; ks < KC / 16; ks++) {
            uint32_t a[4][4], bb[4][2];
            #pragma unroll
            for (int mi = 0; mi < 4; mi++) {
                uint32_t off = (uint32_t)((wm * 64 + mi * 16 + arow) * 128
                                          + (ks * 16 + akh * 8) * 2);
                uint32_t sa = Ab + swz(off);
                asm volatile("ldmatrix.sync.aligned.m8n8.x4.shared.b16 "
                             "{%0,%1,%2,%3}, [%4];"
                             : "=r"(a[mi][0]), "=r"(a[mi][1]),
                               "=r"(a[mi][2]), "=r"(a[mi][3])
                             : "r"(sa));
            }
            #pragma unroll
            for (int nj = 0; nj < 4; nj++) {
                uint32_t off = (uint32_t)((wn * 32 + nj * 8 + brow) * 128
                                          + (ks * 16 + bkh * 8) * 2);
                uint32_t sa = Bb + swz(off);
                asm volatile("ldmatrix.sync.aligned.m8n8.x2.shared.b16 "
                             "{%0,%1}, [%2];"
                             : "=r"(bb[nj][0]), "=r"(bb[nj][1])
                             : "r"(sa));
            }
            #pragma unroll
            for (int mi = 0; mi < 4; mi++)
                #pragma unroll
                for (int nj = 0; nj < 4; nj++) {
                    asm volatile(
                        "mma.sync.aligned.m16n8k16.row.col.f32.f16.f16.f32 "
                        "{%0,%1,%2,%3}, {%4,%5,%6,%7}, {%8,%9}, {%0,%1,%2,%3};"
                        : "+f"(acc[mi][nj][0]), "+f"(acc[mi][nj][1]),
                          "+f"(acc[mi][nj][2]), "+f"(acc[mi][nj][3])
                        : "r"(a[mi][0]), "r"(a[mi][1]),
                          "r"(a[mi][2]), "r"(a[mi][3]),
                          "r"(bb[nj][0]), "r"(bb[nj][1]));
                }
        }
        __syncthreads();   // all warps done with buf (ch&1) before it's refilled
    }

    // -------- epilogue: per-pair hinge loss on register accumulators --------
    const int group = lane >> 2;            // 0..7 (row within 8)
    const int lpair = (lane & 3) * 2;       // col pair base

    float loss = 0.f;
    #pragma unroll
    for (int mi = 0; mi < 4; mi++) {
        #pragma unroll
        for (int h = 0; h < 2; h++) {
            int gi = row0 + wm * 64 + mi * 16 + group + h * 8;
            int ci = g_code[gi];
            #pragma unroll
            for (int nj = 0; nj < 4; nj++) {
                #pragma unroll
                for (int q = 0; q < 2; q++) {
                    int gj = col0 + wn * 32 + nj * 8 + lpair + q;
                    if (gj > gi) {
                        float c = acc[mi][nj][h * 2 + q];   // cosine (pre-normalized)
                        int cj = g_code[gj];
                        float t;
                        if (ci == cj) {
                            t = fmaxf(0.95f - c, 0.f);                 // pos pair
                        } else {
                            float thr = ((ci ^ cj) & 0x100) ? 0.5f : 0.7f;
                            t = fmaxf(c - thr, 0.f);                   // neg pair
                        }
                        loss = fmaf(t, t, loss);
                    }
                }
            }
        }
    }

    // reduce: warp shuffle, then across 8 warps
    #pragma unroll
    for (int off = 16; off; off >>= 1)
        loss += __shfl_xor_sync(0xffffffffu, loss, off);

    __shared__ float red[8];
    if (lane == 0) red[w] = loss;
    __syncthreads();
    if (tid == 0) {
        float s = 0.f;
        #pragma unroll
        for (int i = 0; i < 8; i++) s += red[i];
        atomicAdd(&g_acc, (double)s);
    }
}

// ---------------------------------------------------------------------------
// Kernel 3: finalize
// ---------------------------------------------------------------------------
__global__ void finalize_kernel(float* out) {
    out[0] = (float)(g_acc / NPAIRS);
}

extern "C" void kernel_launch(void* const* d_in, const int* in_sizes, int n_in,
                              void* d_out, int out_size) {
    const float* x      = (const float*)d_in[0];
    const int*   labels = (const int*)d_in[1];
    const int*   anim   = (const int*)d_in[2];
    float*       out    = (float*)d_out;

    prep_kernel<<<512, 256>>>(x, labels, anim);

    const int smem_bytes = 65536;   // 2 bufs x 2 tiles x 16KB
    cudaFuncSetAttribute(gemm_loss_kernel,
                         cudaFuncAttributeMaxDynamicSharedMemorySize, smem_bytes);
    gemm_loss_kernel<<<NTRI, 256, smem_bytes>>>();

    finalize_kernel<<<1, 1>>>(out);
}

// round 9
// speedup vs baseline: 5.0228x; 1.0060x over previous
#include <cuda_runtime.h>
#include <cuda_fp16.h>
#include <cstdint>

// Problem constants
#define BN 4096          // batch
#define DD 512           // feature dim
#define T_TILES 32       // 4096 / 128
#define NTRI   528       // T_TILES*(T_TILES+1)/2
#define NPAIRS 8386560.0

// CTA tile
#define TM 128
#define TN 128
#define KC 64            // k-chunk (fp16 elems) => 128 bytes/row, SW128 swizzle
#define NCHUNK (DD / KC) // 8
#define STAGES 3         // cp.async pipeline depth

// Scratch (no allocations allowed)
__device__ __half    g_xh[BN * DD];   // normalized rows in fp16 (4 MB)
__device__ int       g_code[BN];
__device__ double    g_acc;
__device__ unsigned  g_cnt;

__device__ __forceinline__ uint32_t swz(uint32_t off) {
    // SW128: XOR 16B-chunk bits[4:6] with row bits[7:9]
    return off ^ ((off >> 3) & 0x70);
}

// ---------------------------------------------------------------------------
// Kernel 1: warp per row -> inv-norm, write normalized fp16 row; codes; acc=0
// ---------------------------------------------------------------------------
__global__ void prep_kernel(const float* __restrict__ x,
                            const int* __restrict__ labels,
                            const int* __restrict__ anim) {
    int gtid = blockIdx.x * blockDim.x + threadIdx.x;
    int row  = gtid >> 5;
    int lane = threadIdx.x & 31;

    if (row < BN) {
        const float4* rf4 = reinterpret_cast<const float4*>(x + (size_t)row * DD);
        float s = 0.f;
        #pragma unroll
        for (int k = lane; k < DD / 4; k += 32) {
            float4 v = rf4[k];
            s += v.x * v.x + v.y * v.y + v.z * v.z + v.w * v.w;
        }
        #pragma unroll
        for (int off = 16; off; off >>= 1) s += __shfl_xor_sync(0xffffffffu, s, off);
        float inv = 1.0f / fmaxf(sqrtf(s), 1e-8f);

        uint2* dst = reinterpret_cast<uint2*>(g_xh + (size_t)row * DD);
        #pragma unroll
        for (int k0 = 0; k0 < 4; k0++) {
            int e4 = k0 * 32 + lane;            // float4 index 0..127
            float4 v = rf4[e4];
            __half2 lo = __float22half2_rn(make_float2(v.x * inv, v.y * inv));
            __half2 hi = __float22half2_rn(make_float2(v.z * inv, v.w * inv));
            uint2 packed;
            packed.x = *reinterpret_cast<uint32_t*>(&lo);
            packed.y = *reinterpret_cast<uint32_t*>(&hi);
            dst[e4] = packed;
        }
    }
    if (gtid < BN) {
        int lab = labels[gtid];
        lab = min(max(lab, 0), 15);
        g_code[gtid] = lab | (anim[lab] << 8);
    }
    if (gtid == 0) { g_acc = 0.0; g_cnt = 0u; }
}

// ---------------------------------------------------------------------------
// Kernel 2: fp16 mma.sync gram + fused loss + fused finalize.
// Triangular grid (528 CTAs), 128x128 CTA tile, 8 warps (2x4),
// warp tile 64x32 via mma.m16n8k16.f16.f32.
// 3-stage cp.async pipeline, ONE __syncthreads per chunk.
// ---------------------------------------------------------------------------
extern __shared__ unsigned char smem_dyn[];   // 3 stages x (A 16K | B 16K) = 96 KB

__global__ __launch_bounds__(256, 2)
void gemm_loss_kernel(float* __restrict__ outp) {
    // Decode linear block index b -> (ti, tj), ti <= tj.
    int b = blockIdx.x;
    int tj = (int)((sqrtf(8.0f * (float)b + 1.0f) - 1.0f) * 0.5f);
    while (tj * (tj + 1) / 2 > b) tj--;
    while ((tj + 1) * (tj + 2) / 2 <= b) tj++;
    int ti = b - tj * (tj + 1) / 2;

    const int row0 = ti * TM;
    const int col0 = tj * TN;

    const int tid  = threadIdx.x;
    const int lane = tid & 31;
    const int w    = tid >> 5;
    const int wm   = w >> 2;          // 0..1
    const int wn   = w & 3;           // 0..3

    const uint32_t smem_base = (uint32_t)__cvta_generic_to_shared(smem_dyn);

    float acc[4][4][4];
    #pragma unroll
    for (int i = 0; i < 4; i++)
        #pragma unroll
        for (int j = 0; j < 4; j++)
            #pragma unroll
            for (int c = 0; c < 4; c++) acc[i][j][c] = 0.f;

    // ---- full-tile cp.async issue: 2048 x 16B (8 per thread) ----
    auto issue = [&](int ch, int buf) {
        #pragma unroll
        for (int i = 0; i < 8; i++) {
            int idx  = tid + i * 256;          // 0..2047
            int tile = idx >> 10;              // 0: A(rows), 1: B(cols)
            int t10  = idx & 1023;
            int r    = t10 >> 3;               // 0..127
            int c    = t10 & 7;                // 16B chunk 0..7 (full 128B row)
            int grow = (tile ? col0 : row0) + r;
            const char* gp = reinterpret_cast<const char*>(g_xh)
                           + ((size_t)grow * DD + ch * KC + c * 8) * 2;
            uint32_t sa = smem_base + buf * 32768 + tile * 16384
                        + swz((uint32_t)(r * 128 + c * 16));
            asm volatile("cp.async.cg.shared.global [%0], [%1], 16;\n"
                         :: "r"(sa), "l"(gp));
        }
        asm volatile("cp.async.commit_group;\n" ::);
    };

    // prologue: two chunks in flight
    issue(0, 0);
    issue(1, 1);

    // ldmatrix lane address components
    const int arow = lane & 15;        // A: row within 16
    const int akh  = lane >> 4;        // A: k-half (0/1) -> +8 fp16
    const int brow = lane & 7;         // B: row within 8
    const int bkh  = (lane >> 3) & 1;  // B: k-half

    for (int ch = 0; ch < NCHUNK; ch++) {
        if (ch + 1 < NCHUNK) {
            asm volatile("cp.async.wait_group 1;\n" ::);  // group ch done
        } else {
            asm volatile("cp.async.wait_group 0;\n" ::);  // last chunk
        }
        __syncthreads();   // buffer ch%3 fully visible to all warps

        const uint32_t Ab = smem_base + (uint32_t)((ch % STAGES) * 32768);
        const uint32_t Bb = Ab + 16384;

        #pragma unroll
        for (int ks = 0; ks < KC / 16; ks++) {
            uint32_t a[4][4], bb[4][2];
            #pragma unroll
            for (int mi = 0; mi < 4; mi++) {
                uint32_t off = (uint32_t)((wm * 64 + mi * 16 + arow) * 128
                                          + (ks * 16 + akh * 8) * 2);
                uint32_t sa = Ab + swz(off);
                asm volatile("ldmatrix.sync.aligned.m8n8.x4.shared.b16 "
                             "{%0,%1,%2,%3}, [%4];"
                             : "=r"(a[mi][0]), "=r"(a[mi][1]),
                               "=r"(a[mi][2]), "=r"(a[mi][3])
                             : "r"(sa));
            }
            #pragma unroll
            for (int nj = 0; nj < 4; nj++) {
                uint32_t off = (uint32_t)((wn * 32 + nj * 8 + brow) * 128
                                          + (ks * 16 + bkh * 8) * 2);
                uint32_t sa = Bb + swz(off);
                asm volatile("ldmatrix.sync.aligned.m8n8.x2.shared.b16 "
                             "{%0,%1}, [%2];"
                             : "=r"(bb[nj][0]), "=r"(bb[nj][1])
                             : "r"(sa));
            }
            #pragma unroll
            for (int mi = 0; mi < 4; mi++)
                #pragma unroll
                for (int nj = 0; nj < 4; nj++) {
                    asm volatile(
                        "mma.sync.aligned.m16n8k16.row.col.f32.f16.f16.f32 "
                        "{%0,%1,%2,%3}, {%4,%5,%6,%7}, {%8,%9}, {%0,%1,%2,%3};"
                        : "+f"(acc[mi][nj][0]), "+f"(acc[mi][nj][1]),
                          "+f"(acc[mi][nj][2]), "+f"(acc[mi][nj][3])
                        : "r"(a[mi][0]), "r"(a[mi][1]),
                          "r"(a[mi][2]), "r"(a[mi][3]),
                        "r"(bb[nj][0]), "r"(bb[nj][1]));
                }
        }

        // issue chunk ch+2 into buf (ch+2)%3. Safe without trailing barrier:
        // slowest warp is computing ch on buf ch%3; (ch+2)%3 != ch%3, and all
        // reads of buf (ch+2)%3 (== (ch-1)%3) finished before this iteration's
        // barrier (compute ch-1 precedes it in program order on every warp).
        if (ch + 2 < NCHUNK) issue(ch + 2, (ch + 2) % STAGES);
    }

    // -------- epilogue: per-pair hinge loss on register accumulators --------
    const int group = lane >> 2;            // 0..7 (row within 8)
    const int lpair = (lane & 3) * 2;       // col pair base

    float loss = 0.f;
    #pragma unroll
    for (int mi = 0; mi < 4; mi++) {
        #pragma unroll
        for (int h = 0; h < 2; h++) {
            int gi = row0 + wm * 64 + mi * 16 + group + h * 8;
            int ci = g_code[gi];
            #pragma unroll
            for (int nj = 0; nj < 4; nj++) {
                #pragma unroll
                for (int q = 0; q < 2; q++) {
                    int gj = col0 + wn * 32 + nj * 8 + lpair + q;
                    if (gj > gi) {
                        float c = acc[mi][nj][h * 2 + q];   // cosine (pre-normalized)
                        int cj = g_code[gj];
                        float t;
                        if (ci == cj) {
                            t = fmaxf(0.95f - c, 0.f);                 // pos pair
                        } else {
                            float thr = ((ci ^ cj) & 0x100) ? 0.5f : 0.7f;
                            t = fmaxf(c - thr, 0.f);                   // neg pair
                        }
                        loss = fmaf(t, t, loss);
                    }
                }
            }
        }
    }

    // reduce: warp shuffle, then across 8 warps
    #pragma unroll
    for (int off = 16; off; off >>= 1)
        loss += __shfl_xor_sync(0xffffffffu, loss, off);

    __shared__ float red[8];
    if (lane == 0) red[w] = loss;
    __syncthreads();
    if (tid == 0) {
        float s = 0.f;
        #pragma unroll
        for (int i = 0; i < 8; i++) s += red[i];
        atomicAdd(&g_acc, (double)s);
        // fused finalize: last CTA to finish writes the output
        __threadfence();
        unsigned t = atomicAdd(&g_cnt, 1u);
        if (t == NTRI - 1) {
            outp[0] = (float)(g_acc / NPAIRS);
        }
    }
}

extern "C" void kernel_launch(void* const* d_in, const int* in_sizes, int n_in,
                              void* d_out, int out_size) {
    const float* x      = (const float*)d_in[0];
    const int*   labels = (const int*)d_in[1];
    const int*   anim   = (const int*)d_in[2];
    float*       out    = (float*)d_out;

    prep_kernel<<<512, 256>>>(x, labels, anim);

    const int smem_bytes = STAGES * 32768;   // 96 KB dynamic
    cudaFuncSetAttribute(gemm_loss_kernel,
                         cudaFuncAttributeMaxDynamicSharedMemorySize, smem_bytes);
    gemm_loss_kernel<<<NTRI, 256, smem_bytes>>>(out);
}